// round 5
// baseline (speedup 1.0000x reference)
#include <cuda_runtime.h>
#include <math.h>

#define BATCH 8
#define QLEN 256
#define KLEN 1024
#define DQ   256
#define DV   128
#define H    128

// Scratch (statically allocated device globals — no cudaMalloc).
__device__ float g_qh[BATCH * QLEN * H];          // 1 MB
__device__ float g_kh[BATCH * KLEN * H];          // 4 MB
__device__ float g_sc[BATCH * QLEN * KLEN];       // 8 MB
__device__ unsigned int g_ctr;                    // work-stealing counter

__device__ __forceinline__ float fast_tanh(float x) {
    float y;
    asm("tanh.approx.f32 %0, %1;" : "=f"(y) : "f"(x));
    return y;
}

// ---------------------------------------------------------------------------
// Kernel 1: fused projections qh = Q@Wq, kh = K@Wk.
// 32 output rows x 128 cols per block -> 320 blocks. 256 threads, 4x4 tile.
// Double-buffered smem + register prefetch: one sync per k-chunk, global
// latency overlapped with FMA.
// ---------------------------------------------------------------------------
__global__ __launch_bounds__(256) void proj_kernel(
    const float* __restrict__ Qin, const float* __restrict__ Kin,
    const float* __restrict__ Wq,  const float* __restrict__ Wk)
{
    if (blockIdx.x == 0 && threadIdx.x == 0) g_ctr = 0;  // reset for scores

    __shared__ float Xs[2][32][36];
    __shared__ float Ws[2][32][128];

    int blk = blockIdx.x;
    const float* X; const float* W; float* Y; int r0;
    if (blk < 64) { X = Qin; W = Wq; Y = g_qh; r0 = blk * 32; }
    else          { X = Kin; W = Wk; Y = g_kh; r0 = (blk - 64) * 32; }

    int tid = threadIdx.x;
    int tx = tid & 31;       // -> 4 cols at 4*tx
    int ty = tid >> 5;       // -> 4 rows at 4*ty

    int xr = tid >> 3, xd = (tid & 7) << 2;      // X stage coords

    float acc[4][4] = {};

    // Stage chunk 0 directly
    {
        float4 v = *(const float4*)(X + (size_t)(r0 + xr) * DQ + xd);
        *(float4*)&Xs[0][xr][xd] = v;
        #pragma unroll
        for (int it = 0; it < 4; it++) {
            int i = tid + it * 256;
            int dd = i >> 5, c = (i & 31) << 2;
            *(float4*)&Ws[0][dd][c] = *(const float4*)(W + (size_t)dd * H + c);
        }
    }
    __syncthreads();

    for (int c = 0; c < 8; c++) {
        int cur = c & 1;
        float4 px; float4 pw[4];
        if (c < 7) {
            int d0 = (c + 1) * 32;
            px = *(const float4*)(X + (size_t)(r0 + xr) * DQ + d0 + xd);
            #pragma unroll
            for (int it = 0; it < 4; it++) {
                int i = tid + it * 256;
                int dd = i >> 5, cc = (i & 31) << 2;
                pw[it] = *(const float4*)(W + (size_t)(d0 + dd) * H + cc);
            }
        }

        #pragma unroll
        for (int dd = 0; dd < 32; dd += 4) {
            float4 xrg[4], wv[4];
            #pragma unroll
            for (int i = 0; i < 4; i++)
                xrg[i] = *(const float4*)&Xs[cur][(ty << 2) + i][dd];  // broadcast
            #pragma unroll
            for (int j = 0; j < 4; j++)
                wv[j] = *(const float4*)&Ws[cur][dd + j][tx << 2];
            #pragma unroll
            for (int i = 0; i < 4; i++) {
                float xi[4] = {xrg[i].x, xrg[i].y, xrg[i].z, xrg[i].w};
                #pragma unroll
                for (int j = 0; j < 4; j++) {
                    acc[i][0] = fmaf(xi[j], wv[j].x, acc[i][0]);
                    acc[i][1] = fmaf(xi[j], wv[j].y, acc[i][1]);
                    acc[i][2] = fmaf(xi[j], wv[j].z, acc[i][2]);
                    acc[i][3] = fmaf(xi[j], wv[j].w, acc[i][3]);
                }
            }
        }

        if (c < 7) {
            int nxt = cur ^ 1;
            *(float4*)&Xs[nxt][xr][xd] = px;
            #pragma unroll
            for (int it = 0; it < 4; it++) {
                int i = tid + it * 256;
                int dd = i >> 5, cc = (i & 31) << 2;
                *(float4*)&Ws[nxt][dd][cc] = pw[it];
            }
            __syncthreads();
        }
    }

    #pragma unroll
    for (int i = 0; i < 4; i++) {
        float4 v = make_float4(acc[i][0], acc[i][1], acc[i][2], acc[i][3]);
        *(float4*)(Y + (size_t)(r0 + (ty << 2) + i) * H + (tx << 2)) = v;
    }
}

// ---------------------------------------------------------------------------
// Kernel 2: scores[b,q,k] = sum_h w[h] * tanh(qh[b,q,h] + kh[b,k,h])
// Work item = 32q x 32k tile, only for k-tiles < valid_len (masked tails
// underflow to exact 0 in the reference softmax, so never needed).
// Persistent CTAs pull items via atomic counter. MUFU-bound (near floor).
// ---------------------------------------------------------------------------
__global__ __launch_bounds__(256) void scores_kernel(
    const float* __restrict__ wv_g, const int* __restrict__ valid)
{
    __shared__ float qs[32][36];    // [q][h]  direct copy
    __shared__ float ks[32][33];    // [h][k]  transposed scatter
    __shared__ float wvs[H];
    __shared__ unsigned int s_item;

    int tid = threadIdx.x;
    if (tid < H) wvs[tid] = wv_g[tid];

    int nk[BATCH], off[BATCH + 1];
    off[0] = 0;
    #pragma unroll
    for (int b = 0; b < BATCH; b++) {
        nk[b] = (valid[b] + 31) >> 5;
        off[b + 1] = off[b] + 8 * nk[b];
    }
    unsigned int total = (unsigned int)off[BATCH];

    int tx = tid & 15;      // 2 keys at 2*tx
    int ty = tid >> 4;      // 2 queries at 2*ty

    while (true) {
        __syncthreads();                      // smem reuse + s_item protection
        if (tid == 0) s_item = atomicAdd(&g_ctr, 1u);
        __syncthreads();
        unsigned int w = s_item;
        if (w >= total) break;

        int b = 0;
        #pragma unroll
        for (int bb = 0; bb < BATCH - 1; bb++)
            if (w >= (unsigned int)off[bb + 1]) b = bb + 1;
        int idx   = (int)w - off[b];
        int ktile = idx % nk[b];
        int qtile = idx / nk[b];
        int k0 = ktile << 5, q0 = qtile << 5;

        const float* qbase = g_qh + ((size_t)b * QLEN + q0) * H;
        const float* kbase = g_kh + ((size_t)b * KLEN + k0) * H;

        float acc[2][2] = {};

        for (int h0 = 0; h0 < H; h0 += 32) {
            __syncthreads();
            {
                int r = tid >> 3, hv = (tid & 7) << 2;
                float4 v = *(const float4*)(qbase + (size_t)r * H + h0 + hv);
                *(float4*)&qs[r][hv] = v;
                float4 u = *(const float4*)(kbase + (size_t)r * H + h0 + hv);
                ks[hv + 0][r] = u.x; ks[hv + 1][r] = u.y;
                ks[hv + 2][r] = u.z; ks[hv + 3][r] = u.w;
            }
            __syncthreads();

            #pragma unroll
            for (int hh = 0; hh < 32; hh++) {
                float w0 = wvs[h0 + hh];
                float qa = qs[(ty << 1) + 0][hh];
                float qb = qs[(ty << 1) + 1][hh];
                float ka = ks[hh][(tx << 1) + 0];
                float kb = ks[hh][(tx << 1) + 1];
                acc[0][0] = fmaf(w0, fast_tanh(qa + ka), acc[0][0]);
                acc[0][1] = fmaf(w0, fast_tanh(qa + kb), acc[0][1]);
                acc[1][0] = fmaf(w0, fast_tanh(qb + ka), acc[1][0]);
                acc[1][1] = fmaf(w0, fast_tanh(qb + kb), acc[1][1]);
            }
        }

        float* s0 = g_sc + ((size_t)b * QLEN + q0 + (ty << 1)) * KLEN + k0 + (tx << 1);
        *(float2*)s0          = make_float2(acc[0][0], acc[0][1]);
        *(float2*)(s0 + KLEN) = make_float2(acc[1][0], acc[1][1]);
    }
}

// ---------------------------------------------------------------------------
// Kernel 3 (fused, q-tiled): per 16-q tile, masked softmax stats (pass 1),
// then blocked AV GEMM with probabilities recomputed per 64-k chunk (pass 2).
// V traffic amortized 16x vs per-row kernel (512MB -> 32MB of L2 reads).
// Grid (16 qtiles, 8 batches), 256 threads.
// ---------------------------------------------------------------------------
__global__ __launch_bounds__(256) void softmax_av_kernel(
    const float* __restrict__ values, const int* __restrict__ valid,
    float* __restrict__ out)
{
    __shared__ float Vs[64][128];   // V chunk, 32 KB
    __shared__ float Ps[16][64];    // probabilities chunk
    __shared__ float sm_m[16], sm_l[16];

    int b   = blockIdx.y;
    int q0  = blockIdx.x << 4;
    int vl  = valid[b];
    int tid = threadIdx.x;
    int lane = tid & 31, warp = tid >> 5;

    // ---- Pass 1: per-row max and sum(exp) over k < vl (warp -> 2 rows) ----
    #pragma unroll
    for (int rr = 0; rr < 2; rr++) {
        int r = (warp << 1) + rr;
        const float* srow = g_sc + ((size_t)b * QLEN + q0 + r) * KLEN;
        float m = -3.0e38f;
        for (int k = lane << 2; k < vl; k += 128) {
            float4 s4 = *(const float4*)(srow + k);
            if (k + 0 < vl) m = fmaxf(m, s4.x);
            if (k + 1 < vl) m = fmaxf(m, s4.y);
            if (k + 2 < vl) m = fmaxf(m, s4.z);
            if (k + 3 < vl) m = fmaxf(m, s4.w);
        }
        #pragma unroll
        for (int o = 16; o; o >>= 1) m = fmaxf(m, __shfl_xor_sync(0xffffffffu, m, o));
        float l = 0.f;
        for (int k = lane << 2; k < vl; k += 128) {
            float4 s4 = *(const float4*)(srow + k);
            if (k + 0 < vl) l += __expf(s4.x - m);
            if (k + 1 < vl) l += __expf(s4.y - m);
            if (k + 2 < vl) l += __expf(s4.z - m);
            if (k + 3 < vl) l += __expf(s4.w - m);
        }
        #pragma unroll
        for (int o = 16; o; o >>= 1) l += __shfl_xor_sync(0xffffffffu, l, o);
        if (lane == 0) { sm_m[r] = m; sm_l[r] = l; }
    }
    __syncthreads();

    // ---- Pass 2: chunked AV GEMM ----
    int tx = tid & 31;            // 4 v-cols at 4*tx
    int ty = tid >> 5;            // 2 q-rows at 2*ty
    int prow = tid >> 4, pk = (tid & 15) << 2;   // P staging coords

    float acc[2][4] = {};
    int nch = (vl + 63) >> 6;

    for (int ch = 0; ch < nch; ch++) {
        int k0 = ch << 6;
        __syncthreads();
        // Stage P[16][64]
        {
            const float* srow = g_sc + ((size_t)b * QLEN + q0 + prow) * KLEN + k0 + pk;
            float mr = sm_m[prow];
            float4 s4 = *(const float4*)srow;
            float4 p4;
            p4.x = (k0 + pk + 0 < vl) ? __expf(s4.x - mr) : 0.f;
            p4.y = (k0 + pk + 1 < vl) ? __expf(s4.y - mr) : 0.f;
            p4.z = (k0 + pk + 2 < vl) ? __expf(s4.z - mr) : 0.f;
            p4.w = (k0 + pk + 3 < vl) ? __expf(s4.w - mr) : 0.f;
            *(float4*)&Ps[prow][pk] = p4;
        }
        // Stage V[64][128]
        #pragma unroll
        for (int it = 0; it < 8; it++) {
            int i = tid + it * 256;            // 0..2047 float4s
            int vr = i >> 5, vc = (i & 31) << 2;
            *(float4*)&Vs[vr][vc] =
                *(const float4*)(values + ((size_t)b * KLEN + k0 + vr) * DV + vc);
        }
        __syncthreads();

        int r0 = ty << 1;
        #pragma unroll 4
        for (int kk = 0; kk < 64; kk += 4) {
            float4 pa = *(const float4*)&Ps[r0 + 0][kk];
            float4 pb = *(const float4*)&Ps[r0 + 1][kk];
            float pas[4] = {pa.x, pa.y, pa.z, pa.w};
            float pbs[4] = {pb.x, pb.y, pb.z, pb.w};
            #pragma unroll
            for (int j = 0; j < 4; j++) {
                float4 vv = *(const float4*)&Vs[kk + j][tx << 2];
                acc[0][0] = fmaf(pas[j], vv.x, acc[0][0]);
                acc[0][1] = fmaf(pas[j], vv.y, acc[0][1]);
                acc[0][2] = fmaf(pas[j], vv.z, acc[0][2]);
                acc[0][3] = fmaf(pas[j], vv.w, acc[0][3]);
                acc[1][0] = fmaf(pbs[j], vv.x, acc[1][0]);
                acc[1][1] = fmaf(pbs[j], vv.y, acc[1][1]);
                acc[1][2] = fmaf(pbs[j], vv.z, acc[1][2]);
                acc[1][3] = fmaf(pbs[j], vv.w, acc[1][3]);
            }
        }
    }

    int r0 = ty << 1;
    #pragma unroll
    for (int i = 0; i < 2; i++) {
        float inv = 1.0f / sm_l[r0 + i];
        float4 o4 = make_float4(acc[i][0] * inv, acc[i][1] * inv,
                                acc[i][2] * inv, acc[i][3] * inv);
        *(float4*)(out + ((size_t)b * QLEN + q0 + r0 + i) * DV + (tx << 2)) = o4;
    }
}

// ---------------------------------------------------------------------------
extern "C" void kernel_launch(void* const* d_in, const int* in_sizes, int n_in,
                              void* d_out, int out_size)
{
    const float* queries = (const float*)d_in[0];
    const float* keys    = (const float*)d_in[1];
    const float* values  = (const float*)d_in[2];
    const int*   valid   = (const int*)d_in[3];
    const float* Wq      = (const float*)d_in[4];
    const float* Wk      = (const float*)d_in[5];
    const float* wv      = (const float*)d_in[6];
    float* out = (float*)d_out;

    proj_kernel<<<320, 256>>>(queries, keys, Wq, Wk);
    scores_kernel<<<296, 256>>>(wv, valid);
    softmax_av_kernel<<<dim3(16, 8), 256>>>(values, valid, out);
}

// round 6
// speedup vs baseline: 1.0939x; 1.0939x over previous
#include <cuda_runtime.h>
#include <math.h>

#define BATCH 8
#define QLEN 256
#define KLEN 1024
#define DQ   256
#define DV   128
#define H    128

// Scratch (statically allocated device globals — no cudaMalloc).
__device__ float g_qh[BATCH * QLEN * H];          // 1 MB
__device__ float g_kh[BATCH * KLEN * H];          // 4 MB
__device__ float g_sc[BATCH * QLEN * KLEN];       // 8 MB
__device__ unsigned int g_ctr;                    // work-stealing counter

__device__ __forceinline__ float fast_tanh(float x) {
    float y;
    asm("tanh.approx.f32 %0, %1;" : "=f"(y) : "f"(x));
    return y;
}

// ---------------------------------------------------------------------------
// Kernel 1: fused projections qh = Q@Wq, kh = K@Wk.
// 32 output rows x 128 cols per block -> 320 blocks. 256 threads, 4x4 tile.
// Double-buffered smem + register prefetch.
// ---------------------------------------------------------------------------
__global__ __launch_bounds__(256) void proj_kernel(
    const float* __restrict__ Qin, const float* __restrict__ Kin,
    const float* __restrict__ Wq,  const float* __restrict__ Wk)
{
    if (blockIdx.x == 0 && threadIdx.x == 0) g_ctr = 0;  // reset for scores

    __shared__ float Xs[2][32][36];
    __shared__ float Ws[2][32][128];

    int blk = blockIdx.x;
    const float* X; const float* W; float* Y; int r0;
    if (blk < 64) { X = Qin; W = Wq; Y = g_qh; r0 = blk * 32; }
    else          { X = Kin; W = Wk; Y = g_kh; r0 = (blk - 64) * 32; }

    int tid = threadIdx.x;
    int tx = tid & 31;       // -> 4 cols at 4*tx
    int ty = tid >> 5;       // -> 4 rows at 4*ty

    int xr = tid >> 3, xd = (tid & 7) << 2;      // X stage coords

    float acc[4][4] = {};

    {
        float4 v = *(const float4*)(X + (size_t)(r0 + xr) * DQ + xd);
        *(float4*)&Xs[0][xr][xd] = v;
        #pragma unroll
        for (int it = 0; it < 4; it++) {
            int i = tid + it * 256;
            int dd = i >> 5, c = (i & 31) << 2;
            *(float4*)&Ws[0][dd][c] = *(const float4*)(W + (size_t)dd * H + c);
        }
    }
    __syncthreads();

    for (int c = 0; c < 8; c++) {
        int cur = c & 1;
        float4 px; float4 pw[4];
        if (c < 7) {
            int d0 = (c + 1) * 32;
            px = *(const float4*)(X + (size_t)(r0 + xr) * DQ + d0 + xd);
            #pragma unroll
            for (int it = 0; it < 4; it++) {
                int i = tid + it * 256;
                int dd = i >> 5, cc = (i & 31) << 2;
                pw[it] = *(const float4*)(W + (size_t)(d0 + dd) * H + cc);
            }
        }

        #pragma unroll
        for (int dd = 0; dd < 32; dd += 4) {
            float4 xrg[4], wv[4];
            #pragma unroll
            for (int i = 0; i < 4; i++)
                xrg[i] = *(const float4*)&Xs[cur][(ty << 2) + i][dd];  // broadcast
            #pragma unroll
            for (int j = 0; j < 4; j++)
                wv[j] = *(const float4*)&Ws[cur][dd + j][tx << 2];
            #pragma unroll
            for (int i = 0; i < 4; i++) {
                float xi[4] = {xrg[i].x, xrg[i].y, xrg[i].z, xrg[i].w};
                #pragma unroll
                for (int j = 0; j < 4; j++) {
                    acc[i][0] = fmaf(xi[j], wv[j].x, acc[i][0]);
                    acc[i][1] = fmaf(xi[j], wv[j].y, acc[i][1]);
                    acc[i][2] = fmaf(xi[j], wv[j].z, acc[i][2]);
                    acc[i][3] = fmaf(xi[j], wv[j].w, acc[i][3]);
                }
            }
        }

        if (c < 7) {
            int nxt = cur ^ 1;
            *(float4*)&Xs[nxt][xr][xd] = px;
            #pragma unroll
            for (int it = 0; it < 4; it++) {
                int i = tid + it * 256;
                int dd = i >> 5, cc = (i & 31) << 2;
                *(float4*)&Ws[nxt][dd][cc] = pw[it];
            }
            __syncthreads();
        }
    }

    #pragma unroll
    for (int i = 0; i < 4; i++) {
        float4 v = make_float4(acc[i][0], acc[i][1], acc[i][2], acc[i][3]);
        *(float4*)(Y + (size_t)(r0 + (ty << 2) + i) * H + (tx << 2)) = v;
    }
}

// ---------------------------------------------------------------------------
// Kernel 2: scores[b,q,k] = sum_h w[h] * tanh(qh[b,q,h] + kh[b,k,h])
// 32q x 32k work items for k-tiles < valid_len, work-stealing over
// persistent CTAs. MUFU-bound near floor.
// ---------------------------------------------------------------------------
__global__ __launch_bounds__(256) void scores_kernel(
    const float* __restrict__ wv_g, const int* __restrict__ valid)
{
    __shared__ float qs[32][36];    // [q][h]  direct copy
    __shared__ float ks[32][33];    // [h][k]  transposed scatter
    __shared__ float wvs[H];
    __shared__ unsigned int s_item;

    int tid = threadIdx.x;
    if (tid < H) wvs[tid] = wv_g[tid];

    int nk[BATCH], off[BATCH + 1];
    off[0] = 0;
    #pragma unroll
    for (int b = 0; b < BATCH; b++) {
        nk[b] = (valid[b] + 31) >> 5;
        off[b + 1] = off[b] + 8 * nk[b];
    }
    unsigned int total = (unsigned int)off[BATCH];

    int tx = tid & 15;      // 2 keys at 2*tx
    int ty = tid >> 4;      // 2 queries at 2*ty

    while (true) {
        __syncthreads();                      // smem reuse + s_item protection
        if (tid == 0) s_item = atomicAdd(&g_ctr, 1u);
        __syncthreads();
        unsigned int w = s_item;
        if (w >= total) break;

        int b = 0;
        #pragma unroll
        for (int bb = 0; bb < BATCH - 1; bb++)
            if (w >= (unsigned int)off[bb + 1]) b = bb + 1;
        int idx   = (int)w - off[b];
        int ktile = idx % nk[b];
        int qtile = idx / nk[b];
        int k0 = ktile << 5, q0 = qtile << 5;

        const float* qbase = g_qh + ((size_t)b * QLEN + q0) * H;
        const float* kbase = g_kh + ((size_t)b * KLEN + k0) * H;

        float acc[2][2] = {};

        for (int h0 = 0; h0 < H; h0 += 32) {
            __syncthreads();
            {
                int r = tid >> 3, hv = (tid & 7) << 2;
                float4 v = *(const float4*)(qbase + (size_t)r * H + h0 + hv);
                *(float4*)&qs[r][hv] = v;
                float4 u = *(const float4*)(kbase + (size_t)r * H + h0 + hv);
                ks[hv + 0][r] = u.x; ks[hv + 1][r] = u.y;
                ks[hv + 2][r] = u.z; ks[hv + 3][r] = u.w;
            }
            __syncthreads();

            #pragma unroll
            for (int hh = 0; hh < 32; hh++) {
                float w0 = wvs[h0 + hh];
                float qa = qs[(ty << 1) + 0][hh];
                float qb = qs[(ty << 1) + 1][hh];
                float ka = ks[hh][(tx << 1) + 0];
                float kb = ks[hh][(tx << 1) + 1];
                acc[0][0] = fmaf(w0, fast_tanh(qa + ka), acc[0][0]);
                acc[0][1] = fmaf(w0, fast_tanh(qa + kb), acc[0][1]);
                acc[1][0] = fmaf(w0, fast_tanh(qb + ka), acc[1][0]);
                acc[1][1] = fmaf(w0, fast_tanh(qb + kb), acc[1][1]);
            }
        }

        float* s0 = g_sc + ((size_t)b * QLEN + q0 + (ty << 1)) * KLEN + k0 + (tx << 1);
        *(float2*)s0          = make_float2(acc[0][0], acc[0][1]);
        *(float2*)(s0 + KLEN) = make_float2(acc[1][0], acc[1][1]);
    }
}

// ---------------------------------------------------------------------------
// Kernel 3: fused masked softmax + AV, 4 q-rows per block.
// Grid (64 qtiles, 8 batches) = 512 CTAs x 256 thr -> ~3.5 CTAs/SM of
// overlap, V L2 traffic = 128 MB (4x less than per-row version).
// Pass 1: row stats (2 warps/row). Pass 2: 64-k chunks; each thread owns an
// 8-k split x 4 rows x 4 cols (128 FMA per 8 V LDS.128); 8-way k-split
// reduction through smem at the end (reuses V buffer).
// ---------------------------------------------------------------------------
__global__ __launch_bounds__(256) void softmax_av_kernel(
    const float* __restrict__ values, const int* __restrict__ valid,
    float* __restrict__ out)
{
    __shared__ float Vs[64][128];   // 32 KB V chunk (reused as reduction scratch)
    __shared__ float Ps[4][64];
    __shared__ float pm[8], pl[8];
    __shared__ float sm_m[4], sm_li[4];

    int b   = blockIdx.y;
    int q0  = blockIdx.x << 2;
    int vl  = valid[b];
    int tid = threadIdx.x;
    int lane = tid & 31, warp = tid >> 5;

    // ---- Pass 1: per-row max and sum(exp); 2 warps per row ----
    int r    = warp & 3;
    int part = warp >> 2;
    const float* srow = g_sc + ((size_t)b * QLEN + q0 + r) * KLEN;

    float m = -3.0e38f;
    for (int k = (part * 32 + lane) << 2; k < vl; k += 256) {
        float4 s4 = *(const float4*)(srow + k);
        if (k + 0 < vl) m = fmaxf(m, s4.x);
        if (k + 1 < vl) m = fmaxf(m, s4.y);
        if (k + 2 < vl) m = fmaxf(m, s4.z);
        if (k + 3 < vl) m = fmaxf(m, s4.w);
    }
    #pragma unroll
    for (int o = 16; o; o >>= 1) m = fmaxf(m, __shfl_xor_sync(0xffffffffu, m, o));
    if (lane == 0) pm[warp] = m;
    __syncthreads();
    float mrow = fmaxf(pm[r], pm[r + 4]);

    float l = 0.f;
    for (int k = (part * 32 + lane) << 2; k < vl; k += 256) {
        float4 s4 = *(const float4*)(srow + k);
        if (k + 0 < vl) l += __expf(s4.x - mrow);
        if (k + 1 < vl) l += __expf(s4.y - mrow);
        if (k + 2 < vl) l += __expf(s4.z - mrow);
        if (k + 3 < vl) l += __expf(s4.w - mrow);
    }
    #pragma unroll
    for (int o = 16; o; o >>= 1) l += __shfl_xor_sync(0xffffffffu, l, o);
    if (lane == 0) pl[warp] = l;
    __syncthreads();
    if (tid < 4) {
        sm_m[tid]  = fmaxf(pm[tid], pm[tid + 4]);
        sm_li[tid] = 1.0f / (pl[tid] + pl[tid + 4]);
    }

    // ---- Pass 2: chunked AV ----
    int tx = tid & 31;            // 4 v-cols at 4*tx
    int ty = tid >> 5;            // 8-way k split within chunk
    int prow = tid >> 4, pk = (tid & 15) << 2;   // P staging (threads 0..63)

    float acc[4][4] = {};
    int nch = (vl + 63) >> 6;

    for (int ch = 0; ch < nch; ch++) {
        int k0 = ch << 6;
        __syncthreads();
        if (tid < 64) {
            const float* sr = g_sc + ((size_t)b * QLEN + q0 + prow) * KLEN + k0 + pk;
            float mr = sm_m[prow];
            float4 s4 = *(const float4*)sr;
            float4 p4;
            p4.x = (k0 + pk + 0 < vl) ? __expf(s4.x - mr) : 0.f;
            p4.y = (k0 + pk + 1 < vl) ? __expf(s4.y - mr) : 0.f;
            p4.z = (k0 + pk + 2 < vl) ? __expf(s4.z - mr) : 0.f;
            p4.w = (k0 + pk + 3 < vl) ? __expf(s4.w - mr) : 0.f;
            *(float4*)&Ps[prow][pk] = p4;
        }
        #pragma unroll
        for (int it = 0; it < 8; it++) {
            int i = tid + it * 256;            // 0..2047 float4s
            int vr = i >> 5, vc = (i & 31) << 2;
            *(float4*)&Vs[vr][vc] =
                *(const float4*)(values + ((size_t)b * KLEN + k0 + vr) * DV + vc);
        }
        __syncthreads();

        #pragma unroll
        for (int kk8 = 0; kk8 < 8; kk8++) {
            int kk = (ty << 3) + kk8;
            float4 vv = *(const float4*)&Vs[kk][tx << 2];
            float p0 = Ps[0][kk], p1 = Ps[1][kk], p2 = Ps[2][kk], p3 = Ps[3][kk];
            acc[0][0] = fmaf(p0, vv.x, acc[0][0]);
            acc[0][1] = fmaf(p0, vv.y, acc[0][1]);
            acc[0][2] = fmaf(p0, vv.z, acc[0][2]);
            acc[0][3] = fmaf(p0, vv.w, acc[0][3]);
            acc[1][0] = fmaf(p1, vv.x, acc[1][0]);
            acc[1][1] = fmaf(p1, vv.y, acc[1][1]);
            acc[1][2] = fmaf(p1, vv.z, acc[1][2]);
            acc[1][3] = fmaf(p1, vv.w, acc[1][3]);
            acc[2][0] = fmaf(p2, vv.x, acc[2][0]);
            acc[2][1] = fmaf(p2, vv.y, acc[2][1]);
            acc[2][2] = fmaf(p2, vv.z, acc[2][2]);
            acc[2][3] = fmaf(p2, vv.w, acc[2][3]);
            acc[3][0] = fmaf(p3, vv.x, acc[3][0]);
            acc[3][1] = fmaf(p3, vv.y, acc[3][1]);
            acc[3][2] = fmaf(p3, vv.z, acc[3][2]);
            acc[3][3] = fmaf(p3, vv.w, acc[3][3]);
        }
    }

    // ---- 8-way k-split reduction through smem (reuse Vs) ----
    __syncthreads();
    float4* racc = (float4*)&Vs[0][0];       // [ty][tx][row] : 8*32*4 float4
    #pragma unroll
    for (int i = 0; i < 4; i++)
        racc[((ty << 5) + tx) * 4 + i] =
            make_float4(acc[i][0], acc[i][1], acc[i][2], acc[i][3]);
    __syncthreads();
    if (warp < 4) {                           // warp = row, lane = col group
        float4 s = make_float4(0.f, 0.f, 0.f, 0.f);
        #pragma unroll
        for (int g = 0; g < 8; g++) {
            float4 t = racc[((g << 5) + lane) * 4 + warp];
            s.x += t.x; s.y += t.y; s.z += t.z; s.w += t.w;
        }
        float inv = sm_li[warp];
        s.x *= inv; s.y *= inv; s.z *= inv; s.w *= inv;
        *(float4*)(out + ((size_t)b * QLEN + q0 + warp) * DV + (lane << 2)) = s;
    }
}

// ---------------------------------------------------------------------------
extern "C" void kernel_launch(void* const* d_in, const int* in_sizes, int n_in,
                              void* d_out, int out_size)
{
    const float* queries = (const float*)d_in[0];
    const float* keys    = (const float*)d_in[1];
    const float* values  = (const float*)d_in[2];
    const int*   valid   = (const int*)d_in[3];
    const float* Wq      = (const float*)d_in[4];
    const float* Wk      = (const float*)d_in[5];
    const float* wv      = (const float*)d_in[6];
    float* out = (float*)d_out;

    proj_kernel<<<320, 256>>>(queries, keys, Wq, Wk);
    scores_kernel<<<296, 256>>>(wv, valid);
    softmax_av_kernel<<<dim3(64, 8), 256>>>(values, valid, out);
}

// round 7
// speedup vs baseline: 1.1183x; 1.0222x over previous
#include <cuda_runtime.h>
#include <math.h>

#define BATCH 8
#define QLEN 256
#define KLEN 1024
#define DQ   256
#define DV   128
#define H    128

// Scratch (statically allocated device globals — no cudaMalloc).
__device__ float g_qh[BATCH * QLEN * H];          // 1 MB
__device__ float g_kh[BATCH * KLEN * H];          // 4 MB
__device__ float g_sc[BATCH * QLEN * KLEN];       // 8 MB
__device__ unsigned int g_ctr;                    // work-stealing counter

__device__ __forceinline__ float fast_tanh(float x) {
    float y;
    asm("tanh.approx.f32 %0, %1;" : "=f"(y) : "f"(x));
    return y;
}

// ---------------------------------------------------------------------------
// Kernel 1: fused projections qh = Q@Wq, kh = K@Wk.
// 32 output rows x 64 cols per block -> 640 blocks x 128 threads
// (4.3 CTAs/SM: finer wave granularity than 320x256). 4x4 reg tile,
// double-buffered smem + register prefetch.
// ---------------------------------------------------------------------------
__global__ __launch_bounds__(128) void proj_kernel(
    const float* __restrict__ Qin, const float* __restrict__ Kin,
    const float* __restrict__ Wq,  const float* __restrict__ Wk)
{
    if (blockIdx.x == 0 && threadIdx.x == 0) g_ctr = 0;  // reset for scores

    __shared__ float Xs[2][32][36];
    __shared__ float Ws[2][32][64];

    int blk = blockIdx.x;
    const float* X; const float* W; float* Y; int r0, c0;
    if (blk < 128) { X = Qin; W = Wq; Y = g_qh; r0 = (blk >> 1) * 32; c0 = (blk & 1) * 64; }
    else { int bb = blk - 128; X = Kin; W = Wk; Y = g_kh; r0 = (bb >> 1) * 32; c0 = (bb & 1) * 64; }

    int tid = threadIdx.x;
    int tx = tid & 15;       // -> 4 cols at 4*tx
    int ty = tid >> 4;       // -> 4 rows at 4*ty

    float acc[4][4] = {};

    // Stage chunk 0
    #pragma unroll
    for (int it = 0; it < 2; it++) {
        int i = tid + it * 128;
        int xr = i >> 3, xd = (i & 7) << 2;
        *(float4*)&Xs[0][xr][xd] = *(const float4*)(X + (size_t)(r0 + xr) * DQ + xd);
    }
    #pragma unroll
    for (int it = 0; it < 4; it++) {
        int i = tid + it * 128;
        int dd = i >> 4, c = (i & 15) << 2;
        *(float4*)&Ws[0][dd][c] = *(const float4*)(W + (size_t)dd * H + c0 + c);
    }
    __syncthreads();

    for (int ch = 0; ch < 8; ch++) {
        int cur = ch & 1;
        float4 px[2], pw[4];
        if (ch < 7) {
            int d0 = (ch + 1) * 32;
            #pragma unroll
            for (int it = 0; it < 2; it++) {
                int i = tid + it * 128;
                int xr = i >> 3, xd = (i & 7) << 2;
                px[it] = *(const float4*)(X + (size_t)(r0 + xr) * DQ + d0 + xd);
            }
            #pragma unroll
            for (int it = 0; it < 4; it++) {
                int i = tid + it * 128;
                int dd = i >> 4, c = (i & 15) << 2;
                pw[it] = *(const float4*)(W + (size_t)(d0 + dd) * H + c0 + c);
            }
        }

        #pragma unroll
        for (int dd = 0; dd < 32; dd += 4) {
            float4 xrg[4], wv[4];
            #pragma unroll
            for (int i = 0; i < 4; i++)
                xrg[i] = *(const float4*)&Xs[cur][(ty << 2) + i][dd];  // broadcast
            #pragma unroll
            for (int j = 0; j < 4; j++)
                wv[j] = *(const float4*)&Ws[cur][dd + j][tx << 2];
            #pragma unroll
            for (int i = 0; i < 4; i++) {
                float xi[4] = {xrg[i].x, xrg[i].y, xrg[i].z, xrg[i].w};
                #pragma unroll
                for (int j = 0; j < 4; j++) {
                    acc[i][0] = fmaf(xi[j], wv[j].x, acc[i][0]);
                    acc[i][1] = fmaf(xi[j], wv[j].y, acc[i][1]);
                    acc[i][2] = fmaf(xi[j], wv[j].z, acc[i][2]);
                    acc[i][3] = fmaf(xi[j], wv[j].w, acc[i][3]);
                }
            }
        }

        if (ch < 7) {
            int nxt = cur ^ 1;
            #pragma unroll
            for (int it = 0; it < 2; it++) {
                int i = tid + it * 128;
                int xr = i >> 3, xd = (i & 7) << 2;
                *(float4*)&Xs[nxt][xr][xd] = px[it];
            }
            #pragma unroll
            for (int it = 0; it < 4; it++) {
                int i = tid + it * 128;
                int dd = i >> 4, c = (i & 15) << 2;
                *(float4*)&Ws[nxt][dd][c] = pw[it];
            }
            __syncthreads();
        }
    }

    #pragma unroll
    for (int i = 0; i < 4; i++) {
        float4 v = make_float4(acc[i][0], acc[i][1], acc[i][2], acc[i][3]);
        *(float4*)(Y + (size_t)(r0 + (ty << 2) + i) * H + c0 + (tx << 2)) = v;
    }
}

// ---------------------------------------------------------------------------
// Kernel 2: scores[b,q,k] = sum_h w[h] * tanh(qh[b,q,h] + kh[b,k,h])
// 32q x 32k work items for k-tiles < valid_len, work-stealing over
// persistent CTAs. MUFU-bound near floor.
// ---------------------------------------------------------------------------
__global__ __launch_bounds__(256) void scores_kernel(
    const float* __restrict__ wv_g, const int* __restrict__ valid)
{
    __shared__ float qs[32][36];    // [q][h]  direct copy
    __shared__ float ks[32][33];    // [h][k]  transposed scatter
    __shared__ float wvs[H];
    __shared__ unsigned int s_item;

    int tid = threadIdx.x;
    if (tid < H) wvs[tid] = wv_g[tid];

    int nk[BATCH], off[BATCH + 1];
    off[0] = 0;
    #pragma unroll
    for (int b = 0; b < BATCH; b++) {
        nk[b] = (valid[b] + 31) >> 5;
        off[b + 1] = off[b] + 8 * nk[b];
    }
    unsigned int total = (unsigned int)off[BATCH];

    int tx = tid & 15;      // 2 keys at 2*tx
    int ty = tid >> 4;      // 2 queries at 2*ty

    while (true) {
        __syncthreads();                      // smem reuse + s_item protection
        if (tid == 0) s_item = atomicAdd(&g_ctr, 1u);
        __syncthreads();
        unsigned int w = s_item;
        if (w >= total) break;

        int b = 0;
        #pragma unroll
        for (int bb = 0; bb < BATCH - 1; bb++)
            if (w >= (unsigned int)off[bb + 1]) b = bb + 1;
        int idx   = (int)w - off[b];
        int ktile = idx % nk[b];
        int qtile = idx / nk[b];
        int k0 = ktile << 5, q0 = qtile << 5;

        const float* qbase = g_qh + ((size_t)b * QLEN + q0) * H;
        const float* kbase = g_kh + ((size_t)b * KLEN + k0) * H;

        float acc[2][2] = {};

        for (int h0 = 0; h0 < H; h0 += 32) {
            __syncthreads();
            {
                int r = tid >> 3, hv = (tid & 7) << 2;
                float4 v = *(const float4*)(qbase + (size_t)r * H + h0 + hv);
                *(float4*)&qs[r][hv] = v;
                float4 u = *(const float4*)(kbase + (size_t)r * H + h0 + hv);
                ks[hv + 0][r] = u.x; ks[hv + 1][r] = u.y;
                ks[hv + 2][r] = u.z; ks[hv + 3][r] = u.w;
            }
            __syncthreads();

            #pragma unroll
            for (int hh = 0; hh < 32; hh++) {
                float w0 = wvs[h0 + hh];
                float qa = qs[(ty << 1) + 0][hh];
                float qb = qs[(ty << 1) + 1][hh];
                float ka = ks[hh][(tx << 1) + 0];
                float kb = ks[hh][(tx << 1) + 1];
                acc[0][0] = fmaf(w0, fast_tanh(qa + ka), acc[0][0]);
                acc[0][1] = fmaf(w0, fast_tanh(qa + kb), acc[0][1]);
                acc[1][0] = fmaf(w0, fast_tanh(qb + ka), acc[1][0]);
                acc[1][1] = fmaf(w0, fast_tanh(qb + kb), acc[1][1]);
            }
        }

        float* s0 = g_sc + ((size_t)b * QLEN + q0 + (ty << 1)) * KLEN + k0 + (tx << 1);
        *(float2*)s0          = make_float2(acc[0][0], acc[0][1]);
        *(float2*)(s0 + KLEN) = make_float2(acc[1][0], acc[1][1]);
    }
}

// ---------------------------------------------------------------------------
// Kernel 3: fused masked softmax + AV.
// 8 q-rows x 64 v-cols per CTA: grid (32 qtiles x 2 col-halves, 8 b) =
// 512 CTAs x 256 thr. V L2 traffic = 64 MB; FMA floor ~4us.
// Pass 1: 1 warp per row stats. Pass 2: 64-k chunks, V half-tile 16KB in
// smem, each thread: 4-k split x 8 rows x 4 cols. Reduction: shfl (2-way)
// then smem (8-way).
// ---------------------------------------------------------------------------
__global__ __launch_bounds__(256) void softmax_av_kernel(
    const float* __restrict__ values, const int* __restrict__ valid,
    float* __restrict__ out)
{
    __shared__ float Vs[64][64];    // 16 KB V half-chunk (reused for reduction)
    __shared__ float Ps[8][64];
    __shared__ float sm_m[8], sm_li[8];

    int b    = blockIdx.y;
    int q0   = (blockIdx.x >> 1) << 3;
    int half = blockIdx.x & 1;
    int vl   = valid[b];
    int tid  = threadIdx.x;
    int lane = tid & 31, warp = tid >> 5;

    // ---- Pass 1: per-row max and sum(exp); 1 warp per row ----
    {
        const float* srow = g_sc + ((size_t)b * QLEN + q0 + warp) * KLEN;
        float m = -3.0e38f;
        for (int k = lane << 2; k < vl; k += 128) {
            float4 s4 = *(const float4*)(srow + k);
            if (k + 0 < vl) m = fmaxf(m, s4.x);
            if (k + 1 < vl) m = fmaxf(m, s4.y);
            if (k + 2 < vl) m = fmaxf(m, s4.z);
            if (k + 3 < vl) m = fmaxf(m, s4.w);
        }
        #pragma unroll
        for (int o = 16; o; o >>= 1) m = fmaxf(m, __shfl_xor_sync(0xffffffffu, m, o));
        float l = 0.f;
        for (int k = lane << 2; k < vl; k += 128) {
            float4 s4 = *(const float4*)(srow + k);
            if (k + 0 < vl) l += __expf(s4.x - m);
            if (k + 1 < vl) l += __expf(s4.y - m);
            if (k + 2 < vl) l += __expf(s4.z - m);
            if (k + 3 < vl) l += __expf(s4.w - m);
        }
        #pragma unroll
        for (int o = 16; o; o >>= 1) l += __shfl_xor_sync(0xffffffffu, l, o);
        if (lane == 0) { sm_m[warp] = m; sm_li[warp] = 1.0f / l; }
    }

    // ---- Pass 2: chunked AV over the column half ----
    int tx = tid & 15;            // 4 v-cols at 4*tx (within half)
    int ty = tid >> 4;            // 16-way k split, 4 k each
    const float* vbase = values + (size_t)b * KLEN * DV + half * 64;

    float acc[8][4] = {};
    int nch = (vl + 63) >> 6;

    for (int ch = 0; ch < nch; ch++) {
        int k0 = ch << 6;
        __syncthreads();
        if (tid < 128) {          // stage P[8][64] with exp + mask
            int prow = tid >> 4, pk = (tid & 15) << 2;
            const float* sr = g_sc + ((size_t)b * QLEN + q0 + prow) * KLEN + k0 + pk;
            float mr = sm_m[prow];
            float4 s4 = *(const float4*)sr;
            float4 p4;
            p4.x = (k0 + pk + 0 < vl) ? __expf(s4.x - mr) : 0.f;
            p4.y = (k0 + pk + 1 < vl) ? __expf(s4.y - mr) : 0.f;
            p4.z = (k0 + pk + 2 < vl) ? __expf(s4.z - mr) : 0.f;
            p4.w = (k0 + pk + 3 < vl) ? __expf(s4.w - mr) : 0.f;
            *(float4*)&Ps[prow][pk] = p4;
        }
        #pragma unroll
        for (int it = 0; it < 4; it++) {      // stage V half-tile [64][64]
            int i = tid + it * 256;           // 0..1023 float4s
            int vr = i >> 4, vc = (i & 15) << 2;
            *(float4*)&Vs[vr][vc] =
                *(const float4*)(vbase + (size_t)(k0 + vr) * DV + vc);
        }
        __syncthreads();

        #pragma unroll
        for (int kks = 0; kks < 4; kks++) {
            int kk = (ty << 2) + kks;
            float4 vv = *(const float4*)&Vs[kk][tx << 2];
            #pragma unroll
            for (int r = 0; r < 8; r++) {
                float p = Ps[r][kk];
                acc[r][0] = fmaf(p, vv.x, acc[r][0]);
                acc[r][1] = fmaf(p, vv.y, acc[r][1]);
                acc[r][2] = fmaf(p, vv.z, acc[r][2]);
                acc[r][3] = fmaf(p, vv.w, acc[r][3]);
            }
        }
    }

    // ---- Reduction: shfl combines the warp's 2 ty groups, then 8-way smem ----
    #pragma unroll
    for (int r = 0; r < 8; r++) {
        #pragma unroll
        for (int j = 0; j < 4; j++)
            acc[r][j] += __shfl_xor_sync(0xffffffffu, acc[r][j], 16);
    }
    __syncthreads();                          // Vs reuse safe
    float4* red = (float4*)&Vs[0][0];         // [warp][tx][row] : 8*16*8 float4
    if (lane < 16) {
        #pragma unroll
        for (int r = 0; r < 8; r++)
            red[((warp << 4) + lane) * 8 + r] =
                make_float4(acc[r][0], acc[r][1], acc[r][2], acc[r][3]);
    }
    __syncthreads();
    if (tid < 128) {
        int r = tid >> 4, cx = tid & 15;
        float4 s = make_float4(0.f, 0.f, 0.f, 0.f);
        #pragma unroll
        for (int g = 0; g < 8; g++) {
            float4 t = red[((g << 4) + cx) * 8 + r];
            s.x += t.x; s.y += t.y; s.z += t.z; s.w += t.w;
        }
        float inv = sm_li[r];
        s.x *= inv; s.y *= inv; s.z *= inv; s.w *= inv;
        *(float4*)(out + ((size_t)b * QLEN + q0 + r) * DV + half * 64 + (cx << 2)) = s;
    }
}

// ---------------------------------------------------------------------------
extern "C" void kernel_launch(void* const* d_in, const int* in_sizes, int n_in,
                              void* d_out, int out_size)
{
    const float* queries = (const float*)d_in[0];
    const float* keys    = (const float*)d_in[1];
    const float* values  = (const float*)d_in[2];
    const int*   valid   = (const int*)d_in[3];
    const float* Wq      = (const float*)d_in[4];
    const float* Wk      = (const float*)d_in[5];
    const float* wv      = (const float*)d_in[6];
    float* out = (float*)d_out;

    proj_kernel<<<640, 128>>>(queries, keys, Wq, Wk);
    scores_kernel<<<296, 256>>>(wv, valid);
    softmax_av_kernel<<<dim3(64, 8), 256>>>(values, valid, out);
}

// round 9
// speedup vs baseline: 1.2274x; 1.0976x over previous
#include <cuda_runtime.h>
#include <math.h>

#define BATCH 8
#define QLEN 256
#define KLEN 1024
#define DQ   256
#define DV   128
#define H    128

// Scratch (statically allocated device globals — no cudaMalloc).
__device__ float g_qh[BATCH * QLEN * H];          // 1 MB
__device__ float g_kh[BATCH * KLEN * H];          // 4 MB
__device__ float g_sc[BATCH * QLEN * KLEN];       // 8 MB
__device__ unsigned int g_ctr;                    // work-stealing counter

__device__ __forceinline__ float fast_tanh(float x) {
    float y;
    asm("tanh.approx.f32 %0, %1;" : "=f"(y) : "f"(x));
    return y;
}

// ---------------------------------------------------------------------------
// Kernel 1: fused projections qh = Q@Wq, kh = K@Wk.
// 32 output rows x 64 cols per block -> 640 blocks x 128 threads.
// 4x4 reg tile, double-buffered smem + register prefetch.
// ---------------------------------------------------------------------------
__global__ __launch_bounds__(128) void proj_kernel(
    const float* __restrict__ Qin, const float* __restrict__ Kin,
    const float* __restrict__ Wq,  const float* __restrict__ Wk)
{
    if (blockIdx.x == 0 && threadIdx.x == 0) g_ctr = 0;  // reset for scores

    __shared__ float Xs[2][32][36];
    __shared__ float Ws[2][32][64];

    int blk = blockIdx.x;
    const float* X; const float* W; float* Y; int r0, c0;
    if (blk < 128) { X = Qin; W = Wq; Y = g_qh; r0 = (blk >> 1) * 32; c0 = (blk & 1) * 64; }
    else { int bb = blk - 128; X = Kin; W = Wk; Y = g_kh; r0 = (bb >> 1) * 32; c0 = (bb & 1) * 64; }

    int tid = threadIdx.x;
    int tx = tid & 15;       // -> 4 cols at 4*tx
    int ty = tid >> 4;       // -> 4 rows at 4*ty

    float acc[4][4] = {};

    #pragma unroll
    for (int it = 0; it < 2; it++) {
        int i = tid + it * 128;
        int xr = i >> 3, xd = (i & 7) << 2;
        *(float4*)&Xs[0][xr][xd] = *(const float4*)(X + (size_t)(r0 + xr) * DQ + xd);
    }
    #pragma unroll
    for (int it = 0; it < 4; it++) {
        int i = tid + it * 128;
        int dd = i >> 4, c = (i & 15) << 2;
        *(float4*)&Ws[0][dd][c] = *(const float4*)(W + (size_t)dd * H + c0 + c);
    }
    __syncthreads();

    for (int ch = 0; ch < 8; ch++) {
        int cur = ch & 1;
        float4 px[2], pw[4];
        if (ch < 7) {
            int d0 = (ch + 1) * 32;
            #pragma unroll
            for (int it = 0; it < 2; it++) {
                int i = tid + it * 128;
                int xr = i >> 3, xd = (i & 7) << 2;
                px[it] = *(const float4*)(X + (size_t)(r0 + xr) * DQ + d0 + xd);
            }
            #pragma unroll
            for (int it = 0; it < 4; it++) {
                int i = tid + it * 128;
                int dd = i >> 4, c = (i & 15) << 2;
                pw[it] = *(const float4*)(W + (size_t)(d0 + dd) * H + c0 + c);
            }
        }

        #pragma unroll
        for (int dd = 0; dd < 32; dd += 4) {
            float4 xrg[4], wv[4];
            #pragma unroll
            for (int i = 0; i < 4; i++)
                xrg[i] = *(const float4*)&Xs[cur][(ty << 2) + i][dd];  // broadcast
            #pragma unroll
            for (int j = 0; j < 4; j++)
                wv[j] = *(const float4*)&Ws[cur][dd + j][tx << 2];
            #pragma unroll
            for (int i = 0; i < 4; i++) {
                float xi[4] = {xrg[i].x, xrg[i].y, xrg[i].z, xrg[i].w};
                #pragma unroll
                for (int j = 0; j < 4; j++) {
                    acc[i][0] = fmaf(xi[j], wv[j].x, acc[i][0]);
                    acc[i][1] = fmaf(xi[j], wv[j].y, acc[i][1]);
                    acc[i][2] = fmaf(xi[j], wv[j].z, acc[i][2]);
                    acc[i][3] = fmaf(xi[j], wv[j].w, acc[i][3]);
                }
            }
        }

        if (ch < 7) {
            int nxt = cur ^ 1;
            #pragma unroll
            for (int it = 0; it < 2; it++) {
                int i = tid + it * 128;
                int xr = i >> 3, xd = (i & 7) << 2;
                *(float4*)&Xs[nxt][xr][xd] = px[it];
            }
            #pragma unroll
            for (int it = 0; it < 4; it++) {
                int i = tid + it * 128;
                int dd = i >> 4, c = (i & 15) << 2;
                *(float4*)&Ws[nxt][dd][c] = pw[it];
            }
            __syncthreads();
        }
    }

    #pragma unroll
    for (int i = 0; i < 4; i++) {
        float4 v = make_float4(acc[i][0], acc[i][1], acc[i][2], acc[i][3]);
        *(float4*)(Y + (size_t)(r0 + (ty << 2) + i) * H + c0 + (tx << 2)) = v;
    }
}

// ---------------------------------------------------------------------------
// Kernel 2: scores[b,q,k] = sum_h w[h] * tanh(qh[b,q,h] + kh[b,k,h])
// 32q x 32k work items for k-tiles < valid_len, work-stealing over
// persistent CTAs. MUFU-bound near floor.
// ---------------------------------------------------------------------------
__global__ __launch_bounds__(256) void scores_kernel(
    const float* __restrict__ wv_g, const int* __restrict__ valid)
{
    __shared__ float qs[32][36];    // [q][h]  direct copy
    __shared__ float ks[32][33];    // [h][k]  transposed scatter
    __shared__ float wvs[H];
    __shared__ unsigned int s_item;

    int tid = threadIdx.x;
    if (tid < H) wvs[tid] = wv_g[tid];

    int nk[BATCH], off[BATCH + 1];
    off[0] = 0;
    #pragma unroll
    for (int b = 0; b < BATCH; b++) {
        nk[b] = (valid[b] + 31) >> 5;
        off[b + 1] = off[b] + 8 * nk[b];
    }
    unsigned int total = (unsigned int)off[BATCH];

    int tx = tid & 15;      // 2 keys at 2*tx
    int ty = tid >> 4;      // 2 queries at 2*ty

    while (true) {
        __syncthreads();                      // smem reuse + s_item protection
        if (tid == 0) s_item = atomicAdd(&g_ctr, 1u);
        __syncthreads();
        unsigned int w = s_item;
        if (w >= total) break;

        int b = 0;
        #pragma unroll
        for (int bb = 0; bb < BATCH - 1; bb++)
            if (w >= (unsigned int)off[bb + 1]) b = bb + 1;
        int idx   = (int)w - off[b];
        int ktile = idx % nk[b];
        int qtile = idx / nk[b];
        int k0 = ktile << 5, q0 = qtile << 5;

        const float* qbase = g_qh + ((size_t)b * QLEN + q0) * H;
        const float* kbase = g_kh + ((size_t)b * KLEN + k0) * H;

        float acc[2][2] = {};

        for (int h0 = 0; h0 < H; h0 += 32) {
            __syncthreads();
            {
                int r = tid >> 3, hv = (tid & 7) << 2;
                float4 v = *(const float4*)(qbase + (size_t)r * H + h0 + hv);
                *(float4*)&qs[r][hv] = v;
                float4 u = *(const float4*)(kbase + (size_t)r * H + h0 + hv);
                ks[hv + 0][r] = u.x; ks[hv + 1][r] = u.y;
                ks[hv + 2][r] = u.z; ks[hv + 3][r] = u.w;
            }
            __syncthreads();

            #pragma unroll
            for (int hh = 0; hh < 32; hh++) {
                float w0 = wvs[h0 + hh];
                float qa = qs[(ty << 1) + 0][hh];
                float qb = qs[(ty << 1) + 1][hh];
                float ka = ks[hh][(tx << 1) + 0];
                float kb = ks[hh][(tx << 1) + 1];
                acc[0][0] = fmaf(w0, fast_tanh(qa + ka), acc[0][0]);
                acc[0][1] = fmaf(w0, fast_tanh(qa + kb), acc[0][1]);
                acc[1][0] = fmaf(w0, fast_tanh(qb + ka), acc[1][0]);
                acc[1][1] = fmaf(w0, fast_tanh(qb + kb), acc[1][1]);
            }
        }

        float* s0 = g_sc + ((size_t)b * QLEN + q0 + (ty << 1)) * KLEN + k0 + (tx << 1);
        *(float2*)s0          = make_float2(acc[0][0], acc[0][1]);
        *(float2*)(s0 + KLEN) = make_float2(acc[1][0], acc[1][1]);
    }
}

// ---------------------------------------------------------------------------
// Kernel 3: fused softmax + AV, SINGLE PASS, no max subtraction.
// |score| <= sum_h |w_h| (~9) since tanh in [-1,1], so exp() cannot overflow
// fp32 and exp(s)/sum(exp(s)) == reference's max-subtracted softmax.
// 8 q-rows x 64 v-cols per CTA: grid (32 qtiles x 2 halves, 8 b) = 512 CTAs.
// 64-k chunks, double-buffered V+P smem with register prefetch (one sync per
// chunk). Ps read as float4 rows (8 LDS.128/chunk, not 32 scalar). Row sums
// accumulated during P staging.
// ---------------------------------------------------------------------------
__global__ __launch_bounds__(256) void softmax_av_kernel(
    const float* __restrict__ values, const int* __restrict__ valid,
    float* __restrict__ out)
{
    __shared__ float Vs[2][64][64];   // 32 KB double-buffered V half-chunk
    __shared__ float Ps[2][8][64];    // 4 KB probabilities
    __shared__ float sm_li[8];

    int b    = blockIdx.y;
    int q0   = (blockIdx.x >> 1) << 3;
    int half = blockIdx.x & 1;
    int vl   = valid[b];
    int tid  = threadIdx.x;
    int lane = tid & 31, warp = tid >> 5;

    int tx = tid & 15;            // 4 v-cols at 4*tx (within half)
    int ty = tid >> 4;            // 16-way k split, 4 k each
    const float* vbase = values + (size_t)b * KLEN * DV + half * 64;

    int prow = tid >> 4, pk = (tid & 15) << 2;    // P staging (tid<128)
    const float* sbase = g_sc + ((size_t)b * QLEN + q0) * KLEN;

    float acc[8][4] = {};
    float lsum = 0.f;
    int nch = (vl + 63) >> 6;

    // ---- prologue: stage chunk 0 ----
    if (tid < 128) {
        float4 s4 = *(const float4*)(sbase + (size_t)prow * KLEN + pk);
        float4 p4;
        p4.x = (pk + 0 < vl) ? __expf(s4.x) : 0.f;
        p4.y = (pk + 1 < vl) ? __expf(s4.y) : 0.f;
        p4.z = (pk + 2 < vl) ? __expf(s4.z) : 0.f;
        p4.w = (pk + 3 < vl) ? __expf(s4.w) : 0.f;
        lsum += p4.x + p4.y + p4.z + p4.w;
        *(float4*)&Ps[0][prow][pk] = p4;
    }
    #pragma unroll
    for (int it = 0; it < 4; it++) {
        int i = tid + it * 256;
        int vr = i >> 4, vc = (i & 15) << 2;
        *(float4*)&Vs[0][vr][vc] = *(const float4*)(vbase + (size_t)vr * DV + vc);
    }
    __syncthreads();

    for (int ch = 0; ch < nch; ch++) {
        int cur = ch & 1, nxt = cur ^ 1;
        bool more = (ch + 1 < nch);
        int k1 = (ch + 1) << 6;

        // prefetch next chunk into registers
        float4 ps4, pv[4];
        if (more) {
            if (tid < 128)
                ps4 = *(const float4*)(sbase + (size_t)prow * KLEN + k1 + pk);
            #pragma unroll
            for (int it = 0; it < 4; it++) {
                int i = tid + it * 256;
                int vr = i >> 4, vc = (i & 15) << 2;
                pv[it] = *(const float4*)(vbase + (size_t)(k1 + vr) * DV + vc);
            }
        }

        // load P rows for this thread's k-group as float4 (8 LDS.128)
        float pr[8][4];
        #pragma unroll
        for (int r = 0; r < 8; r++) {
            float4 t = *(const float4*)&Ps[cur][r][ty << 2];
            pr[r][0] = t.x; pr[r][1] = t.y; pr[r][2] = t.z; pr[r][3] = t.w;
        }

        #pragma unroll
        for (int kks = 0; kks < 4; kks++) {
            float4 vv = *(const float4*)&Vs[cur][(ty << 2) + kks][tx << 2];
            #pragma unroll
            for (int r = 0; r < 8; r++) {
                float p = pr[r][kks];
                acc[r][0] = fmaf(p, vv.x, acc[r][0]);
                acc[r][1] = fmaf(p, vv.y, acc[r][1]);
                acc[r][2] = fmaf(p, vv.z, acc[r][2]);
                acc[r][3] = fmaf(p, vv.w, acc[r][3]);
            }
        }

        if (more) {
            if (tid < 128) {
                float4 p4;
                p4.x = (k1 + pk + 0 < vl) ? __expf(ps4.x) : 0.f;
                p4.y = (k1 + pk + 1 < vl) ? __expf(ps4.y) : 0.f;
                p4.z = (k1 + pk + 2 < vl) ? __expf(ps4.z) : 0.f;
                p4.w = (k1 + pk + 3 < vl) ? __expf(ps4.w) : 0.f;
                lsum += p4.x + p4.y + p4.z + p4.w;
                *(float4*)&Ps[nxt][prow][pk] = p4;
            }
            #pragma unroll
            for (int it = 0; it < 4; it++) {
                int i = tid + it * 256;
                int vr = i >> 4, vc = (i & 15) << 2;
                *(float4*)&Vs[nxt][vr][vc] = pv[it];
            }
        }
        __syncthreads();
    }

    // ---- row-sum reduction (16-lane groups of staging threads) ----
    #pragma unroll
    for (int o = 8; o; o >>= 1) lsum += __shfl_xor_sync(0xffffffffu, lsum, o);
    if (tid < 128 && (lane & 15) == 0) sm_li[prow] = 1.0f / lsum;

    // ---- acc reduction: shfl (ty pair within warp), then 8-way smem ----
    #pragma unroll
    for (int r = 0; r < 8; r++)
        #pragma unroll
        for (int j = 0; j < 4; j++)
            acc[r][j] += __shfl_xor_sync(0xffffffffu, acc[r][j], 16);

    __syncthreads();                          // Vs/Ps reuse + sm_li visible
    float4* red = (float4*)&Vs[0][0][0];      // [r][warp][cx] : 8*8*16 float4
    if (lane < 16) {
        #pragma unroll
        for (int r = 0; r < 8; r++)
            red[(r * 8 + warp) * 16 + lane] =
                make_float4(acc[r][0], acc[r][1], acc[r][2], acc[r][3]);
    }
    __syncthreads();
    if (tid < 128) {
        int r = tid >> 4, cx = tid & 15;
        float4 s = make_float4(0.f, 0.f, 0.f, 0.f);
        #pragma unroll
        for (int g = 0; g < 8; g++) {
            float4 t = red[(r * 8 + g) * 16 + cx];
            s.x += t.x; s.y += t.y; s.z += t.z; s.w += t.w;
        }
        float inv = sm_li[r];
        s.x *= inv; s.y *= inv; s.z *= inv; s.w *= inv;
        *(float4*)(out + ((size_t)b * QLEN + q0 + r) * DV + half * 64 + (cx << 2)) = s;
    }
}

// ---------------------------------------------------------------------------
extern "C" void kernel_launch(void* const* d_in, const int* in_sizes, int n_in,
                              void* d_out, int out_size)
{
    const float* queries = (const float*)d_in[0];
    const float* keys    = (const float*)d_in[1];
    const float* values  = (const float*)d_in[2];
    const int*   valid   = (const int*)d_in[3];
    const float* Wq      = (const float*)d_in[4];
    const float* Wk      = (const float*)d_in[5];
    const float* wv      = (const float*)d_in[6];
    float* out = (float*)d_out;

    proj_kernel<<<640, 128>>>(queries, keys, Wq, Wk);
    scores_kernel<<<296, 256>>>(wv, valid);
    softmax_av_kernel<<<dim3(64, 8), 256>>>(values, valid, out);
}